// round 9
// baseline (speedup 1.0000x reference)
#include <cuda_runtime.h>

// Simulate_22497038696790 — batched dual-phase RK4 RSV model.
// R9: role-split threads (2x16384), ALL-SCALAR (FFMA2 measured rt~4 => packed
// chains are issue-bound and never beat scalar):
//   role A (blocks [0,nA)):  full phase-1  5->21, 48 steps, stores phase-1
//   role B (blocks [nA,2nA)): head 5->15 (no stores) + phase-2 15->31,
//                             63 steps total = structural critical-path floor
// Overhead kills: no local arrays (days read via __ldg in-loop), 32-bit
// addressing, dt-folded rates, distributed RK4 accumulation.
// State substitution T = 1 - D - E:
//   T' = -beta*V*T ; E' = beta*V*T - delta*E ; V' = p*E - c*V
// NSUB=3 (validated: rel_err 3.25e-4 vs 1e-3 threshold).
// Output: [2, 4, 17, B] f32, index = ((phase*4 + comp)*17 + seg)*B + b

#define NSUB 3
#define NT 17
#define BLOCK 128

// ---------------- scalar RK4 (distributed accumulation, dt-folded) ----------
static __device__ __forceinline__ void rk4s(float &T, float &E, float &V,
                                            float bd, float ndd, float pd, float ncd)
{
    const float H = 0.5f, S = 1.0f / 6.0f, TH = 1.0f / 3.0f;
    float q1 = bd * V * T;
    float e1 = fmaf(ndd, E, q1);
    float v1 = fmaf(pd, E, ncd * V);
    float Ta = fmaf(-S, q1, T), Ea = fmaf(S, e1, E), Va = fmaf(S, v1, V);
    float Tm = fmaf(-H, q1, T), Em = fmaf(H, e1, E), Vm = fmaf(H, v1, V);
    float q2 = bd * Vm * Tm;
    float e2 = fmaf(ndd, Em, q2);
    float v2 = fmaf(pd, Em, ncd * Vm);
    Ta = fmaf(-TH, q2, Ta); Ea = fmaf(TH, e2, Ea); Va = fmaf(TH, v2, Va);
    Tm = fmaf(-H, q2, T);  Em = fmaf(H, e2, E);  Vm = fmaf(H, v2, V);
    float q3 = bd * Vm * Tm;
    float e3 = fmaf(ndd, Em, q3);
    float v3 = fmaf(pd, Em, ncd * Vm);
    Ta = fmaf(-TH, q3, Ta); Ea = fmaf(TH, e3, Ea); Va = fmaf(TH, v3, Va);
    Tm = fmaf(-1.0f, q3, T); Em = E + e3; Vm = V + v3;
    float q4 = bd * Vm * Tm;
    float e4 = fmaf(ndd, Em, q4);
    float v4 = fmaf(pd, Em, ncd * Vm);
    T = fmaf(-S, q4, Ta); E = fmaf(S, e4, Ea); V = fmaf(S, v4, Va);
}

static __device__ __forceinline__ void seg_scalar(
    float &T, float &E, float &V, float dt,
    float beta, float delta, float p, float c)
{
    if (dt == 0.0f) return;
    float bd  = beta * dt;
    float ndd = -delta * dt;
    float pd  = p * dt;
    float ncd = -c * dt;
#pragma unroll
    for (int k = 0; k < NSUB; ++k) rk4s(T, E, V, bd, ndd, pd, ncd);
}

__global__ __launch_bounds__(BLOCK)
void Simulate_22497038696790_kernel(
    const float* __restrict__ days1, const float* __restrict__ days2,
    const float* __restrict__ D0,   const float* __restrict__ E0,
    const float* __restrict__ V01,  const float* __restrict__ V02,
    const float* __restrict__ beta_, const float* __restrict__ delta_,
    const float* __restrict__ p_,    const float* __restrict__ c_,
    const int* __restrict__ treatment,
    float* __restrict__ out, int B, int nA)
{
    const bool roleB = (blockIdx.x >= (unsigned)nA);
    const int  blk   = roleB ? (blockIdx.x - nA) : blockIdx.x;
    const int  b     = blk * BLOCK + threadIdx.x;
    if (b >= B) return;

    const float beta  = beta_[b];
    const float delta = delta_[b];
    const float p     = p_[b];
    const float c     = c_[b];
    const int   treat = treatment[0];

    // first index where days1 == 15.0 (jnp.argmax semantics: 0 if none)
    int idx15 = 0;
#pragma unroll
    for (int i = NT - 1; i >= 0; i--) if (__ldg(days1 + i) == 15.0f) idx15 = i;

    float E = E0[b];
    float T = 1.0f - D0[b] - E;
    float V = treat ? V01[b] : 0.0f;

    const unsigned uB      = (unsigned)B;
    const unsigned strideC = (unsigned)NT * uB;
    const unsigned ub      = (unsigned)b;

    float t = 5.0f;

    if (!roleB) {
        // ---- Role A: full phase-1 (5 -> 21), store all phase-1 saves ----
        for (int s = 0; s < NT; ++s) {
            float tn = __ldg(days1 + s);
            seg_scalar(T, E, V, (tn - t) * (1.0f / NSUB), beta, delta, p, c);
            t = tn;
            unsigned base = (unsigned)s * uB + ub;             // phase 0
            out[base]               = 1.0f - T - E;
            out[base + 1 * strideC] = E;
            out[base + 2 * strideC] = V;
            out[base + 3 * strideC] = __logf(V);
        }
    } else {
        // ---- Role B: head 5 -> 15 (no stores) ----
        for (int s = 0; s <= idx15; ++s) {
            float tn = __ldg(days1 + s);
            seg_scalar(T, E, V, (tn - t) * (1.0f / NSUB), beta, delta, p, c);
            t = tn;
        }
        // Day-15 restart (treatment bolus)
        if (treat) V += V02[b];
        t = 15.0f;
        // ---- Phase-2 (15 -> 31), store all phase-2 saves ----
        const unsigned phase1off = 4u * strideC;
        for (int s = 0; s < NT; ++s) {
            float tn = __ldg(days2 + s);
            seg_scalar(T, E, V, (tn - t) * (1.0f / NSUB), beta, delta, p, c);
            t = tn;
            unsigned base = phase1off + (unsigned)s * uB + ub; // phase 1
            out[base]               = 1.0f - T - E;
            out[base + 1 * strideC] = E;
            out[base + 2 * strideC] = V;
            out[base + 3 * strideC] = __logf(V);
        }
    }
}

extern "C" void kernel_launch(void* const* d_in, const int* in_sizes, int n_in,
                              void* d_out, int out_size)
{
    const float* days1 = (const float*)d_in[0];
    const float* days2 = (const float*)d_in[1];
    const float* D0    = (const float*)d_in[2];
    const float* E0    = (const float*)d_in[3];
    const float* V01   = (const float*)d_in[4];
    const float* V02   = (const float*)d_in[5];
    const float* beta  = (const float*)d_in[6];
    const float* delta = (const float*)d_in[7];
    const float* p     = (const float*)d_in[8];
    const float* c     = (const float*)d_in[9];
    const int*   treat = (const int*)d_in[10];

    int B  = in_sizes[2];
    int nA = (B + BLOCK - 1) / BLOCK;
    Simulate_22497038696790_kernel<<<2 * nA, BLOCK>>>(
        days1, days2, D0, E0, V01, V02, beta, delta, p, c, treat,
        (float*)d_out, B, nA);
}

// round 10
// speedup vs baseline: 1.1831x; 1.1831x over previous
#include <cuda_runtime.h>

// Simulate_22497038696790 — batched dual-phase RK4 RSV model.
// R10: R8 structure (512 warps = 1/SMSP; scalar head, packed mid, scalar
// tail; NSUB=3) + overhead kills:
//   - day-value prefetch pipeline (tn_next loaded one segment ahead; the
//     ~39cy L1 latency hides under the previous segment's steps instead of
//     sitting on the serial chain 28 times)
//   - 32-bit unsigned addressing from a per-thread base pointer
// Proven facts: scalar RK4 step = 41 ops = 82cy issue ~= latency => 1 warp
// saturates an SMSP; packed FFMA2 rt~4 => packing is issue-neutral (used in
// mid only to cover two distinct chains). Step budget 102 is structural.
// State substitution T = 1 - D - E:
//   T' = -beta*V*T ; E' = beta*V*T - delta*E ; V' = p*E - c*V
// Output: [2, 4, 17, B] f32, index = ((phase*4 + comp)*17 + seg)*B + b

#define NSUB 3
#define NT 17
#define BLOCK 128

typedef unsigned long long u64;

static __device__ __forceinline__ u64 pk(float lo, float hi) {
    u64 r; asm("mov.b64 %0, {%1, %2};" : "=l"(r) : "f"(lo), "f"(hi)); return r;
}
static __device__ __forceinline__ void upk(u64 v, float &lo, float &hi) {
    asm("mov.b64 {%0, %1}, %2;" : "=f"(lo), "=f"(hi) : "l"(v));
}
static __device__ __forceinline__ u64 f2fma(u64 a, u64 b, u64 c) {
    u64 d; asm("fma.rn.f32x2 %0, %1, %2, %3;" : "=l"(d) : "l"(a), "l"(b), "l"(c)); return d;
}
static __device__ __forceinline__ u64 f2mul(u64 a, u64 b) {
    u64 d; asm("mul.rn.f32x2 %0, %1, %2;" : "=l"(d) : "l"(a), "l"(b)); return d;
}
static __device__ __forceinline__ u64 f2add(u64 a, u64 b) {
    u64 d; asm("add.rn.f32x2 %0, %1, %2;" : "=l"(d) : "l"(a), "l"(b)); return d;
}

// ---------------- scalar RK4 (distributed accumulation, dt-folded) ----------
static __device__ __forceinline__ void rk4s(float &T, float &E, float &V,
                                            float bd, float ndd, float pd, float ncd)
{
    const float H = 0.5f, S = 1.0f / 6.0f, TH = 1.0f / 3.0f;
    float q1 = bd * V * T;
    float e1 = fmaf(ndd, E, q1);
    float v1 = fmaf(pd, E, ncd * V);
    float Ta = fmaf(-S, q1, T), Ea = fmaf(S, e1, E), Va = fmaf(S, v1, V);
    float Tm = fmaf(-H, q1, T), Em = fmaf(H, e1, E), Vm = fmaf(H, v1, V);
    float q2 = bd * Vm * Tm;
    float e2 = fmaf(ndd, Em, q2);
    float v2 = fmaf(pd, Em, ncd * Vm);
    Ta = fmaf(-TH, q2, Ta); Ea = fmaf(TH, e2, Ea); Va = fmaf(TH, v2, Va);
    Tm = fmaf(-H, q2, T);  Em = fmaf(H, e2, E);  Vm = fmaf(H, v2, V);
    float q3 = bd * Vm * Tm;
    float e3 = fmaf(ndd, Em, q3);
    float v3 = fmaf(pd, Em, ncd * Vm);
    Ta = fmaf(-TH, q3, Ta); Ea = fmaf(TH, e3, Ea); Va = fmaf(TH, v3, Va);
    Tm = fmaf(-1.0f, q3, T); Em = E + e3; Vm = V + v3;
    float q4 = bd * Vm * Tm;
    float e4 = fmaf(ndd, Em, q4);
    float v4 = fmaf(pd, Em, ncd * Vm);
    T = fmaf(-S, q4, Ta); E = fmaf(S, e4, Ea); V = fmaf(S, v4, Va);
}

static __device__ __forceinline__ void seg_scalar(
    float &T, float &E, float &V, float dt,
    float beta, float delta, float p, float c)
{
    if (dt == 0.0f) return;
    float bd  = beta * dt;
    float ndd = -delta * dt;
    float pd  = p * dt;
    float ncd = -c * dt;
#pragma unroll
    for (int k = 0; k < NSUB; ++k) rk4s(T, E, V, bd, ndd, pd, ncd);
}

// ---------------- packed RK4 (same distributed form) ------------------------
struct K2 { u64 half, nhalf, sixth, nsixth, third, nthird, none; };

static __device__ __forceinline__ void seg_packed(
    u64 &T, u64 &E, u64 &V, float dtA, float dtB,
    u64 b2, u64 nd2, u64 p2, u64 nc2, const K2 &kc)
{
    if (dtA == 0.0f && dtB == 0.0f) return;
    const u64 dt2 = pk(dtA, dtB);
    const u64 bd  = f2mul(b2, dt2);
    const u64 ndd = f2mul(nd2, dt2);
    const u64 pd  = f2mul(p2, dt2);
    const u64 ncd = f2mul(nc2, dt2);

#pragma unroll
    for (int k = 0; k < NSUB; ++k) {
        u64 q1 = f2mul(f2mul(bd, V), T);
        u64 e1 = f2fma(ndd, E, q1);
        u64 v1 = f2fma(pd, E, f2mul(ncd, V));
        u64 Ta = f2fma(kc.nsixth, q1, T);
        u64 Ea = f2fma(kc.sixth, e1, E);
        u64 Va = f2fma(kc.sixth, v1, V);
        u64 Tm = f2fma(kc.nhalf, q1, T);
        u64 Em = f2fma(kc.half, e1, E);
        u64 Vm = f2fma(kc.half, v1, V);
        u64 q2 = f2mul(f2mul(bd, Vm), Tm);
        u64 e2 = f2fma(ndd, Em, q2);
        u64 v2 = f2fma(pd, Em, f2mul(ncd, Vm));
        Ta = f2fma(kc.nthird, q2, Ta);
        Ea = f2fma(kc.third, e2, Ea);
        Va = f2fma(kc.third, v2, Va);
        Tm = f2fma(kc.nhalf, q2, T);
        Em = f2fma(kc.half, e2, E);
        Vm = f2fma(kc.half, v2, V);
        u64 q3 = f2mul(f2mul(bd, Vm), Tm);
        u64 e3 = f2fma(ndd, Em, q3);
        u64 v3 = f2fma(pd, Em, f2mul(ncd, Vm));
        Ta = f2fma(kc.nthird, q3, Ta);
        Ea = f2fma(kc.third, e3, Ea);
        Va = f2fma(kc.third, v3, Va);
        Tm = f2fma(kc.none, q3, T);
        Em = f2add(E, e3);
        Vm = f2add(V, v3);
        u64 q4 = f2mul(f2mul(bd, Vm), Tm);
        u64 e4 = f2fma(ndd, Em, q4);
        u64 v4 = f2fma(pd, Em, f2mul(ncd, Vm));
        T = f2fma(kc.nsixth, q4, Ta);
        E = f2fma(kc.sixth, e4, Ea);
        V = f2fma(kc.sixth, v4, Va);
    }
}

__global__ __launch_bounds__(BLOCK)
void Simulate_22497038696790_kernel(
    const float* __restrict__ days1, const float* __restrict__ days2,
    const float* __restrict__ D0,   const float* __restrict__ E0,
    const float* __restrict__ V01,  const float* __restrict__ V02,
    const float* __restrict__ beta_, const float* __restrict__ delta_,
    const float* __restrict__ p_,    const float* __restrict__ c_,
    const int* __restrict__ treatment,
    float* __restrict__ out, int B)
{
    int b = blockIdx.x * BLOCK + threadIdx.x;
    if (b >= B) return;

    const float beta  = beta_[b];
    const float delta = delta_[b];
    const float p     = p_[b];
    const float c     = c_[b];
    const int   treat = treatment[0];

    // first index where days1 == 15.0 (jnp.argmax semantics: 0 if none)
    int idx15 = 0;
#pragma unroll
    for (int i = NT - 1; i >= 0; i--) if (__ldg(days1 + i) == 15.0f) idx15 = i;

    const unsigned uB      = (unsigned)B;
    const unsigned strideC = (unsigned)NT * uB;
    float* const   o       = out + (unsigned)b;        // thread base pointer

    // ---- Section 1: HEAD, scalar chain, phase-1 segments 0..idx15 ----
    float E1 = E0[b];
    float T1 = 1.0f - D0[b] - E1;
    float V1 = treat ? V01[b] : 0.0f;

    float t = 5.0f;
    float tn = __ldg(days1 + 0);                       // prefetched
    for (int s = 0; s <= idx15; ++s) {
        float tn_next = __ldg(days1 + s + 1);          // prefetch next (off-chain)
        seg_scalar(T1, E1, V1, (tn - t) * (1.0f / NSUB), beta, delta, p, c);
        t = tn;
        tn = tn_next;
        unsigned base = (unsigned)s * uB;              // phase 0
        o[base]               = 1.0f - T1 - E1;
        o[base + 1 * strideC] = E1;
        o[base + 2 * strideC] = V1;
        o[base + 3 * strideC] = __logf(V1);
    }

    // ---- Day-15 restart ----
    float T2 = T1, E2 = E1;
    float V2 = treat ? (V1 + V02[b]) : V1;

    // ---- Section 2: MID, packed; lane0 = phase-1 rem, lane1 = phase-2 ----
    const u64 b2  = pk(beta, beta);
    const u64 nd2 = pk(-delta, -delta);
    const u64 p2  = pk(p, p);
    const u64 nc2 = pk(-c, -c);
    K2 kc;
    kc.half   = pk(0.5f, 0.5f);
    kc.nhalf  = pk(-0.5f, -0.5f);
    kc.sixth  = pk(1.0f / 6.0f, 1.0f / 6.0f);
    kc.nsixth = pk(-1.0f / 6.0f, -1.0f / 6.0f);
    kc.third  = pk(1.0f / 3.0f, 1.0f / 3.0f);
    kc.nthird = pk(-1.0f / 3.0f, -1.0f / 3.0f);
    kc.none   = pk(-1.0f, -1.0f);

    int n1rem = NT - 1 - idx15;                        // paired segment count

    u64 T = pk(T1, T2), E = pk(E1, E2), V = pk(V1, V2);
    float tA = t, tB = 15.0f;
    int   sA = idx15 + 1;
    int   s2 = 0;
    float tnA = tn;                                    // = days1[idx15+1] (prefetched)
    float tnB = __ldg(days2 + 0);
    for (; s2 < n1rem; ++s2) {
        float tnA_n = __ldg(days1 + sA + 1);           // prefetch (may read past; NT reg pad below)
        float tnB_n = __ldg(days2 + s2 + 1);
        float dtA = (tnA - tA) * (1.0f / NSUB);
        float dtB = (tnB - tB) * (1.0f / NSUB);

        seg_packed(T, E, V, dtA, dtB, b2, nd2, p2, nc2, kc);

        float Tl, Th, El, Eh, Vl, Vh;
        upk(T, Tl, Th); upk(E, El, Eh); upk(V, Vl, Vh);
        unsigned base1 = (unsigned)sA * uB;            // phase 0
        o[base1]               = 1.0f - Tl - El;
        o[base1 + 1 * strideC] = El;
        o[base1 + 2 * strideC] = Vl;
        o[base1 + 3 * strideC] = __logf(Vl);
        unsigned base2 = 4u * strideC + (unsigned)s2 * uB;  // phase 1
        o[base2]               = 1.0f - Th - Eh;
        o[base2 + 1 * strideC] = Eh;
        o[base2 + 2 * strideC] = Vh;
        o[base2 + 3 * strideC] = __logf(Vh);

        tA = tnA; tnA = tnA_n; ++sA;
        tB = tnB; tnB = tnB_n;
    }

    // ---- Section 3: END, scalar chain, phase-2 segments n1rem..NT-1 ----
    {
        float Tl, Th, El, Eh, Vl, Vh;
        upk(T, Tl, Th); upk(E, El, Eh); upk(V, Vl, Vh);
        T2 = Th; E2 = Eh; V2 = Vh;
    }
    for (; s2 < NT; ++s2) {
        float tnB_n = __ldg(days2 + s2 + 1);           // prefetch next
        seg_scalar(T2, E2, V2, (tnB - tB) * (1.0f / NSUB), beta, delta, p, c);
        tB = tnB;
        tnB = tnB_n;
        unsigned base = 4u * strideC + (unsigned)s2 * uB;   // phase 1
        o[base]               = 1.0f - T2 - E2;
        o[base + 1 * strideC] = E2;
        o[base + 2 * strideC] = V2;
        o[base + 3 * strideC] = __logf(V2);
    }
}

extern "C" void kernel_launch(void* const* d_in, const int* in_sizes, int n_in,
                              void* d_out, int out_size)
{
    const float* days1 = (const float*)d_in[0];
    const float* days2 = (const float*)d_in[1];
    const float* D0    = (const float*)d_in[2];
    const float* E0    = (const float*)d_in[3];
    const float* V01   = (const float*)d_in[4];
    const float* V02   = (const float*)d_in[5];
    const float* beta  = (const float*)d_in[6];
    const float* delta = (const float*)d_in[7];
    const float* p     = (const float*)d_in[8];
    const float* c     = (const float*)d_in[9];
    const int*   treat = (const int*)d_in[10];

    int B = in_sizes[2];
    int grid = (B + BLOCK - 1) / BLOCK;
    Simulate_22497038696790_kernel<<<grid, BLOCK>>>(
        days1, days2, D0, E0, V01, V02, beta, delta, p, c, treat,
        (float*)d_out, B);
}